// round 3
// baseline (speedup 1.0000x reference)
#include <cuda_runtime.h>
#include <cuda_bf16.h>
#include <cstdint>
#include <cstddef>

#define B_ 64
#define Q_ 256
#define D_ 768
#define THRESH 0.9f
#define MARGIN 0.02f          // >> bf16 screen error bound (~0.004*ni*nj)
#define EPSN 1e-12f
#define QW (Q_/32)

#define TM 128                // tile size (m and n)
#define BK 32                 // k slab
#define SROW 20               // smem row stride in u32 (16 data + 4 pad)

#define CAND_MAX (B_*(Q_*(Q_-1)/2))
__device__ int  g_ncand;      // zero at entry (module init / k_finish cleanup)
__device__ int2 g_cand[CAND_MAX];

// ---------------------------------------------------------------------------
// Kernel 1: fully fused. Per (tile-pair, batch) block:
//  - streams fp32 rows, converts to bf16 smem tiles
//  - accumulates row sumsq during load (in-block norms, no prep pass)
//  - diagonal blocks write the input->output copy while streaming
//  - bf16 HMMA Gram; conservative screen -> candidate list
// grid = (3 upper-tri pairs of 128-row groups, 64 batches), 256 threads.
// ---------------------------------------------------------------------------
__global__ void __launch_bounds__(256, 2) k_sim(const float* __restrict__ in,
                                                float* __restrict__ out) {
    int p = blockIdx.x;                 // 0:(0,0) 1:(0,1) 2:(1,1)
    int ti = (p == 2) ? 1 : 0;
    int tj = (p == 0) ? 0 : 1;
    bool diag = (ti == tj);
    int b = blockIdx.y;

    const float* Ab = in + ((size_t)b * Q_ + ti * TM) * D_;
    const float* Bb = in + ((size_t)b * Q_ + tj * TM) * D_;

    __shared__ uint32_t As[TM * SROW];
    __shared__ uint32_t Bs[TM * SROW];
    __shared__ float nA[TM], nB[TM];

    int t    = threadIdx.x;
    int lane = t & 31;
    int warp = t >> 5;
    int r    = t >> 1;                  // load row 0..127
    int h    = t & 1;                   // half of the 32-col slab
    int mw   = warp >> 1;               // 0..3
    int nw   = warp & 1;                // 0..1
    int m0   = mw * 32;
    int n0   = nw * 64;
    bool skipmma = diag && (nw == 0) && (mw >= 2);   // entirely lower triangle

    float acc[2][8][4];
    #pragma unroll
    for (int f = 0; f < 2; f++)
        #pragma unroll
        for (int g = 0; g < 8; g++)
            #pragma unroll
            for (int c = 0; c < 4; c++) acc[f][g][c] = 0.f;

    const float4* aP = (const float4*)(Ab + (size_t)r * D_ + h * 16);
    const float4* bP = (const float4*)(Bb + (size_t)r * D_ + h * 16);
    float4*       oP = (float4*)(out + ((size_t)b * Q_ + ti * TM + r) * D_ + h * 16);

    float aS = 0.f, bS = 0.f;
    float4 av[4], bv[4];
    #pragma unroll
    for (int q = 0; q < 4; q++) av[q] = aP[q];
    if (!diag) {
        #pragma unroll
        for (int q = 0; q < 4; q++) bv[q] = bP[q];
    }

    for (int k0 = 0; k0 < D_; k0 += BK) {
        __syncthreads();   // previous slab's frag reads done
        uint32_t* dA = As + r * SROW + h * 8;
        #pragma unroll
        for (int q = 0; q < 4; q++) {
            float4 v = av[q];
            aS += v.x*v.x + v.y*v.y + v.z*v.z + v.w*v.w;
            __nv_bfloat162 lo = __floats2bfloat162_rn(v.x, v.y);
            __nv_bfloat162 hi = __floats2bfloat162_rn(v.z, v.w);
            dA[q*2 + 0] = *(unsigned*)&lo;
            dA[q*2 + 1] = *(unsigned*)&hi;
        }
        if (diag) {
            #pragma unroll
            for (int q = 0; q < 4; q++) oP[(k0 >> 2) + q] = av[q];
        } else {
            uint32_t* dB = Bs + r * SROW + h * 8;
            #pragma unroll
            for (int q = 0; q < 4; q++) {
                float4 v = bv[q];
                bS += v.x*v.x + v.y*v.y + v.z*v.z + v.w*v.w;
                __nv_bfloat162 lo = __floats2bfloat162_rn(v.x, v.y);
                __nv_bfloat162 hi = __floats2bfloat162_rn(v.z, v.w);
                dB[q*2 + 0] = *(unsigned*)&lo;
                dB[q*2 + 1] = *(unsigned*)&hi;
            }
        }
        __syncthreads();

        // prefetch next slab while MMAs run
        if (k0 + BK < D_) {
            int idx = (k0 + BK) >> 2;
            #pragma unroll
            for (int q = 0; q < 4; q++) av[q] = aP[idx + q];
            if (!diag) {
                #pragma unroll
                for (int q = 0; q < 4; q++) bv[q] = bP[idx + q];
            }
        }

        if (!skipmma) {
            const uint32_t* BsR = diag ? As : Bs;
            #pragma unroll
            for (int kk = 0; kk < BK; kk += 16) {
                uint32_t af[2][4];
                #pragma unroll
                for (int f = 0; f < 2; f++) {
                    int aw = (m0 + f*16 + (lane >> 2)) * SROW + (kk >> 1) + (lane & 3);
                    af[f][0] = As[aw];
                    af[f][1] = As[aw + 8*SROW];
                    af[f][2] = As[aw + 4];
                    af[f][3] = As[aw + 8*SROW + 4];
                }
                #pragma unroll
                for (int g = 0; g < 8; g++) {
                    int bw = (n0 + g*8 + (lane >> 2)) * SROW + (kk >> 1) + (lane & 3);
                    uint32_t b0 = BsR[bw], b1 = BsR[bw + 4];
                    #pragma unroll
                    for (int f = 0; f < 2; f++) {
                        asm volatile(
                            "mma.sync.aligned.m16n8k16.row.col.f32.bf16.bf16.f32 "
                            "{%0,%1,%2,%3}, {%4,%5,%6,%7}, {%8,%9}, {%0,%1,%2,%3};\n"
                            : "+f"(acc[f][g][0]), "+f"(acc[f][g][1]),
                              "+f"(acc[f][g][2]), "+f"(acc[f][g][3])
                            : "r"(af[f][0]), "r"(af[f][1]), "r"(af[f][2]), "r"(af[f][3]),
                              "r"(b0), "r"(b1));
                    }
                }
            }
        }
    }

    // in-block norms
    aS += __shfl_xor_sync(0xFFFFFFFFu, aS, 1);
    if (!diag) bS += __shfl_xor_sync(0xFFFFFFFFu, bS, 1);
    __syncthreads();
    if (h == 0) {
        nA[r] = fmaxf(sqrtf(aS), EPSN);
        if (!diag) nB[r] = fmaxf(sqrtf(bS), EPSN);
    }
    __syncthreads();

    const float* nBR = diag ? nA : nB;
    #pragma unroll
    for (int f = 0; f < 2; f++) {
        #pragma unroll
        for (int g = 0; g < 8; g++) {
            #pragma unroll
            for (int c = 0; c < 4; c++) {
                int lm = m0 + f*16 + (lane >> 2) + ((c & 2) ? 8 : 0);
                int ln = n0 + g*8 + (lane & 3)*2 + (c & 1);
                int i = ti*TM + lm;
                int j = tj*TM + ln;
                if (j > i && acc[f][g][c] > (THRESH - MARGIN) * nA[lm] * nBR[ln]) {
                    int idx = atomicAdd(&g_ncand, 1);
                    if (idx < CAND_MAX) g_cand[idx] = make_int2(b, i*Q_ + j);
                }
            }
        }
    }
}

// ---------------------------------------------------------------------------
// Kernel 2: recheck (exact fp32, warp/candidate) + merge + state cleanup.
// Single block, 1024 threads. Flags live in smem only.
// ---------------------------------------------------------------------------
__global__ void k_finish(const float* __restrict__ in, float* __restrict__ out) {
    __shared__ unsigned fl[Q_*QW];
    __shared__ int s_any;
    int t = threadIdx.x;
    for (int w = t; w < Q_*QW; w += 1024) fl[w] = 0u;
    if (t == 0) s_any = 0;
    __syncthreads();

    int n = g_ncand;
    if (n > CAND_MAX) n = CAND_MAX;
    int warp = t >> 5, lane = t & 31;
    for (int c = warp; c < n; c += 32) {
        int2 cd = g_cand[c];
        int b = cd.x, i = cd.y >> 8, j = cd.y & 255;
        const float4* pi = (const float4*)(in + ((size_t)b*Q_ + i) * D_);
        const float4* pj = (const float4*)(in + ((size_t)b*Q_ + j) * D_);
        float sd = 0.f, si = 0.f, sj = 0.f;
        #pragma unroll
        for (int q = 0; q < 6; q++) {
            float4 x = pi[lane + 32*q], y = pj[lane + 32*q];
            sd += x.x*y.x + x.y*y.y + x.z*y.z + x.w*y.w;
            si += x.x*x.x + x.y*x.y + x.z*x.z + x.w*x.w;
            sj += y.x*y.x + y.y*y.y + y.z*y.z + y.w*y.w;
        }
        #pragma unroll
        for (int o = 16; o; o >>= 1) {
            sd += __shfl_xor_sync(0xFFFFFFFFu, sd, o);
            si += __shfl_xor_sync(0xFFFFFFFFu, si, o);
            sj += __shfl_xor_sync(0xFFFFFFFFu, sj, o);
        }
        if (lane == 0) {
            float ni = fmaxf(sqrtf(si), EPSN);
            float nj = fmaxf(sqrtf(sj), EPSN);
            if (sd > THRESH * ni * nj) {
                atomicOr(&fl[i*QW + (j >> 5)], 1u << (j & 31));
                s_any = 1;
            }
        }
    }
    __syncthreads();
    if (t == 0) g_ncand = 0;   // restore invariant for next graph replay
    if (s_any == 0) return;

    // sequential merge, reference order (i outer, j inner)
    for (int i = 0; i < Q_ - 1; i++) {
        for (int w = 0; w < QW; w++) {
            unsigned m = fl[i*QW + w];
            while (m) {
                int j = w*32 + __ffs(m) - 1;
                m &= m - 1;
                for (int e = t; e < B_*D_; e += 1024) {
                    int b = e / D_, d = e % D_;
                    size_t oi = (size_t)b*Q_*D_ + (size_t)i*D_ + d;
                    size_t oj = (size_t)b*Q_*D_ + (size_t)j*D_ + d;
                    float nv = 0.5f * (out[oi] + out[oj]);
                    out[oi] = nv;
                    out[oj] = nv;
                }
                __syncthreads();
            }
        }
    }
}

// ---------------------------------------------------------------------------
extern "C" void kernel_launch(void* const* d_in, const int* in_sizes, int n_in,
                              void* d_out, int out_size) {
    (void)in_sizes; (void)n_in; (void)out_size;
    const float* c = (const float*)d_in[0];
    float* out = (float*)d_out;

    dim3 g(3, B_);
    k_sim<<<g, 256>>>(c, out);
    k_finish<<<1, 1024>>>(c, out);
}

// round 12
// speedup vs baseline: 1.3430x; 1.3430x over previous
#include <cuda_runtime.h>
#include <cuda_bf16.h>
#include <cstdint>
#include <cstddef>

#define B_ 64
#define Q_ 256
#define D_ 768
#define THRESH 0.9f
#define MARGIN 0.02f
#define EPSN 1e-12f
#define QW (Q_/32)
#define NS (D_/32)            // 24 k-slabs of 32

#define CAND_MAX (B_*(Q_*(Q_-1)/2))
__device__ int  g_ncand;                       // zeroed at module load + by k_finish
__device__ int2 g_cand[CAND_MAX];
__device__ float g_norm[B_*Q_];
__device__ __align__(16) __nv_bfloat16 g_bf[(size_t)B_*Q_*D_];

// ---------------------------------------------------------------------------
// Kernel 1: fused row norms + input->output copy + fp32->bf16 staging.
// warp per row.
// ---------------------------------------------------------------------------
__global__ void k_prep(const float* __restrict__ in, float* __restrict__ out) {
    int row  = blockIdx.x * 8 + (threadIdx.x >> 5);
    int lane = threadIdx.x & 31;
    const float4* p = (const float4*)(in + (size_t)row * D_);
    float4*       o = (float4*)(out + (size_t)row * D_);
    uint2*       bp = (uint2*)(g_bf + (size_t)row * D_);
    float s = 0.f;
    #pragma unroll
    for (int i = 0; i < 6; i++) {
        float4 v = p[lane + 32*i];
        o[lane + 32*i] = v;
        __nv_bfloat162 lo = __floats2bfloat162_rn(v.x, v.y);
        __nv_bfloat162 hi = __floats2bfloat162_rn(v.z, v.w);
        uint2 u; u.x = *(unsigned*)&lo; u.y = *(unsigned*)&hi;
        bp[lane + 32*i] = u;
        s += v.x*v.x + v.y*v.y + v.z*v.z + v.w*v.w;
    }
    #pragma unroll
    for (int off = 16; off; off >>= 1) s += __shfl_xor_sync(0xFFFFFFFFu, s, off);
    if (lane == 0) g_norm[row] = fmaxf(sqrtf(s), EPSN);
}

// ---------------------------------------------------------------------------
// Kernel 2: bf16 HMMA Gram screen, 64x64 tiles, upper triangle (10 pairs).
// cp.async triple-buffered global->smem; ldmatrix.x4 fragment loads.
// 8 warps, warp tile 16x32.
// ---------------------------------------------------------------------------
#define RSTRIDE 80   // bytes per smem row (64 data + 16 pad): conflict-free
#define SLAB    (64*RSTRIDE)

__device__ __forceinline__ void cp16(uint32_t dst, const void* src) {
    asm volatile("cp.async.cg.shared.global [%0], [%1], 16;\n"
                 :: "r"(dst), "l"(src));
}
__device__ __forceinline__ void cp_commit() {
    asm volatile("cp.async.commit_group;\n");
}

__global__ void __launch_bounds__(256) k_sim() {
    int p = blockIdx.x;
    int ti, tj;
    if      (p < 4) { ti = 0; tj = p;     }
    else if (p < 7) { ti = 1; tj = p - 3; }
    else if (p < 9) { ti = 2; tj = p - 5; }
    else            { ti = 3; tj = 3;     }
    bool diag = (ti == tj);
    int b = blockIdx.y;

    __shared__ __align__(16) uint8_t smA[3][SLAB];
    __shared__ __align__(16) uint8_t smB[3][SLAB];

    int t    = threadIdx.x;
    int lane = t & 31;
    int warp = t >> 5;
    int m0   = (warp >> 1) * 16;
    int n0   = (warp & 1) * 32;
    bool skipw = diag && (n0 == 0) && (m0 >= 32);

    // copy mapping: thread -> (row 0..63, 16B chunk 0..3)
    int cr = t >> 2, cc = t & 3;
    const __nv_bfloat16* aSrc = g_bf + ((size_t)b*Q_ + ti*64 + cr) * D_ + cc*8;
    const __nv_bfloat16* bSrc = g_bf + ((size_t)b*Q_ + tj*64 + cr) * D_ + cc*8;
    uint32_t sA = (uint32_t)__cvta_generic_to_shared(smA);
    uint32_t sB = (uint32_t)__cvta_generic_to_shared(smB);
    uint32_t dOff = cr * RSTRIDE + cc * 16;

    float acc[4][4];
    #pragma unroll
    for (int g = 0; g < 4; g++)
        #pragma unroll
        for (int c = 0; c < 4; c++) acc[g][c] = 0.f;

    // ldmatrix lane addressing (byte offsets within a slab buffer)
    int arow = m0 + ((lane >> 3) & 1) * 8 + (lane & 7);
    int aOff = arow * RSTRIDE + (lane >> 4) * 16;            // + kw*32
    int brow0 = n0 + ((lane >> 4) ? 8 : 0) + (lane & 7);     // g-pair base rows
    int bOff  = brow0 * RSTRIDE + ((lane >> 3) & 1) * 16;    // + kw*32 (+16*RSTRIDE for g=2)

    // prologue: slabs 0,1
    #pragma unroll
    for (int s = 0; s < 2; s++) {
        cp16(sA + s*SLAB + dOff, (const uint8_t*)aSrc + s*64);
        if (!diag) cp16(sB + s*SLAB + dOff, (const uint8_t*)bSrc + s*64);
        cp_commit();
    }

    for (int s = 0; s < NS; s++) {
        if (s + 1 < NS) asm volatile("cp.async.wait_group 1;\n");
        else            asm volatile("cp.async.wait_group 0;\n");
        __syncthreads();
        if (s + 2 < NS) {
            int nb = (s + 2) % 3;
            cp16(sA + nb*SLAB + dOff, (const uint8_t*)aSrc + (s+2)*64);
            if (!diag) cp16(sB + nb*SLAB + dOff, (const uint8_t*)bSrc + (s+2)*64);
            cp_commit();
        }
        if (!skipw) {
            uint32_t aBase = sA + (s % 3) * SLAB;
            uint32_t bBase = diag ? aBase : sB + (s % 3) * SLAB;
            #pragma unroll
            for (int kw = 0; kw < 2; kw++) {
                uint32_t a0, a1, a2, a3;
                asm volatile(
                    "ldmatrix.sync.aligned.m8n8.x4.shared.b16 {%0,%1,%2,%3}, [%4];\n"
                    : "=r"(a0), "=r"(a1), "=r"(a2), "=r"(a3)
                    : "r"(aBase + aOff + kw*32));
                #pragma unroll
                for (int gp = 0; gp < 2; gp++) {   // g pairs {0,1},{2,3}
                    uint32_t b0, b1, b2, b3;
                    asm volatile(
                        "ldmatrix.sync.aligned.m8n8.x4.shared.b16 {%0,%1,%2,%3}, [%4];\n"
                        : "=r"(b0), "=r"(b1), "=r"(b2), "=r"(b3)
                        : "r"(bBase + bOff + kw*32 + gp*16*RSTRIDE));
                    int g = gp * 2;
                    asm volatile(
                        "mma.sync.aligned.m16n8k16.row.col.f32.bf16.bf16.f32 "
                        "{%0,%1,%2,%3}, {%4,%5,%6,%7}, {%8,%9}, {%0,%1,%2,%3};\n"
                        : "+f"(acc[g][0]), "+f"(acc[g][1]),
                          "+f"(acc[g][2]), "+f"(acc[g][3])
                        : "r"(a0), "r"(a1), "r"(a2), "r"(a3), "r"(b0), "r"(b1));
                    asm volatile(
                        "mma.sync.aligned.m16n8k16.row.col.f32.bf16.bf16.f32 "
                        "{%0,%1,%2,%3}, {%4,%5,%6,%7}, {%8,%9}, {%0,%1,%2,%3};\n"
                        : "+f"(acc[g+1][0]), "+f"(acc[g+1][1]),
                          "+f"(acc[g+1][2]), "+f"(acc[g+1][3])
                        : "r"(a0), "r"(a1), "r"(a2), "r"(a3), "r"(b2), "r"(b3));
                }
            }
        }
    }

    const float* nrm = g_norm + b * Q_;
    #pragma unroll
    for (int g = 0; g < 4; g++) {
        #pragma unroll
        for (int c = 0; c < 4; c++) {
            int i = ti*64 + m0 + (lane >> 2) + ((c & 2) ? 8 : 0);
            int j = tj*64 + n0 + g*8 + (lane & 3)*2 + (c & 1);
            if (j > i && acc[g][c] > (THRESH - MARGIN) * nrm[i] * nrm[j]) {
                int idx = atomicAdd(&g_ncand, 1);
                if (idx < CAND_MAX) g_cand[idx] = make_int2(b, i*Q_ + j);
            }
        }
    }
}

// ---------------------------------------------------------------------------
// Kernel 3: exact fp32 recheck + sequential merge + cleanup. One block.
// ---------------------------------------------------------------------------
__global__ void k_finish(const float* __restrict__ in, float* __restrict__ out) {
    __shared__ unsigned fl[Q_*QW];
    __shared__ int s_any;
    int t = threadIdx.x;
    for (int w = t; w < Q_*QW; w += 1024) fl[w] = 0u;
    if (t == 0) s_any = 0;
    __syncthreads();

    int n = g_ncand;
    if (n > CAND_MAX) n = CAND_MAX;
    int warp = t >> 5, lane = t & 31;
    for (int c = warp; c < n; c += 32) {
        int2 cd = g_cand[c];
        int b = cd.x, i = cd.y >> 8, j = cd.y & 255;
        const float4* pi = (const float4*)(in + ((size_t)b*Q_ + i) * D_);
        const float4* pj = (const float4*)(in + ((size_t)b*Q_ + j) * D_);
        float sd = 0.f, si = 0.f, sj = 0.f;
        #pragma unroll
        for (int q = 0; q < 6; q++) {
            float4 x = pi[lane + 32*q], y = pj[lane + 32*q];
            sd += x.x*y.x + x.y*y.y + x.z*y.z + x.w*y.w;
            si += x.x*x.x + x.y*x.y + x.z*x.z + x.w*x.w;
            sj += y.x*y.x + y.y*y.y + y.z*y.z + y.w*y.w;
        }
        #pragma unroll
        for (int o = 16; o; o >>= 1) {
            sd += __shfl_xor_sync(0xFFFFFFFFu, sd, o);
            si += __shfl_xor_sync(0xFFFFFFFFu, si, o);
            sj += __shfl_xor_sync(0xFFFFFFFFu, sj, o);
        }
        if (lane == 0) {
            float ni = fmaxf(sqrtf(si), EPSN);
            float nj = fmaxf(sqrtf(sj), EPSN);
            if (sd > THRESH * ni * nj) {
                atomicOr(&fl[i*QW + (j >> 5)], 1u << (j & 31));
                s_any = 1;
            }
        }
    }
    __syncthreads();
    if (t == 0) g_ncand = 0;
    if (s_any == 0) return;

    for (int i = 0; i < Q_ - 1; i++) {
        for (int w = 0; w < QW; w++) {
            unsigned m = fl[i*QW + w];
            while (m) {
                int j = w*32 + __ffs(m) - 1;
                m &= m - 1;
                for (int e = t; e < B_*D_; e += 1024) {
                    int b = e / D_, d = e % D_;
                    size_t oi = (size_t)b*Q_*D_ + (size_t)i*D_ + d;
                    size_t oj = (size_t)b*Q_*D_ + (size_t)j*D_ + d;
                    float nv = 0.5f * (out[oi] + out[oj]);
                    out[oi] = nv;
                    out[oj] = nv;
                }
                __syncthreads();
            }
        }
    }
}

// ---------------------------------------------------------------------------
extern "C" void kernel_launch(void* const* d_in, const int* in_sizes, int n_in,
                              void* d_out, int out_size) {
    (void)in_sizes; (void)n_in; (void)out_size;
    const float* c = (const float*)d_in[0];
    float* out = (float*)d_out;

    k_prep<<<(B_*Q_)/8, 256>>>(c, out);
    dim3 g(10, B_);
    k_sim<<<g, 256>>>();
    k_finish<<<1, 1024>>>(c, out);
}